// round 5
// baseline (speedup 1.0000x reference)
#include <cuda_runtime.h>
#include <cuda_fp16.h>
#include <cstdint>

#define M_TOK 64
#define N_OUT 8192
#define K_IN  8192
#define NG    64             // K groups per row
#define WTOTAL 8192          // 128 ntiles * 64 groups
#define NCTA  148            // 1 per SM, all resident (persistent)
#define NTHREADS 256
#define BK    128
#define RING  4
#define WROW  528            // raw wq row stride bytes (512 data + 16 pad)
#define WSTAGE (64 * WROW)   // 33792 B raw weights per stage
#define LDK   136
#define ASTAGE (M_TOK * LDK * 2)  // 17408 B x tile per stage
#define SMEM_BYTES (RING * (WSTAGE + ASTAGE))  // 204800 B

__device__ __half   g_xh[M_TOK * K_IN];       // x in fp16
__device__ uint32_t g_szp[NG * N_OUT];        // packed (s,z) half2
__device__ float    g_part[NCTA * 2 * 4096];  // stream-K partials
__device__ unsigned g_syncctr[2];             // grid-sync tickets (monotonic across replays)

__device__ __forceinline__ int gsplit(int c) { return (int)(((long long)c * WTOTAL) / NCTA); }

__device__ __forceinline__ void grid_sync(int k) {
    __syncthreads();
    if (threadIdx.x == 0) {
        __threadfence();
        unsigned t = atomicAdd(&g_syncctr[k], 1u) + 1u;
        unsigned target = ((t + NCTA - 1u) / NCTA) * NCTA;
        while (atomicAdd(&g_syncctr[k], 0u) < target) __nanosleep(64);
        __threadfence();
    }
    __syncthreads();
}

__device__ __forceinline__ void cp16(uint32_t dst, const void* src) {
    asm volatile("cp.async.cg.shared.global [%0], [%1], 16;" :: "r"(dst), "l"(src));
}
__device__ __forceinline__ void lds2(uint32_t& a, uint32_t& b, uint32_t addr) {
    asm volatile("ld.shared.v2.u32 {%0,%1}, [%2];" : "=r"(a), "=r"(b) : "r"(addr));
}
__device__ __forceinline__ void ldsm4(uint32_t& r0, uint32_t& r1, uint32_t& r2, uint32_t& r3,
                                      uint32_t a) {
    asm volatile("ldmatrix.sync.aligned.m8n8.x4.shared.b16 {%0,%1,%2,%3}, [%4];"
                 : "=r"(r0), "=r"(r1), "=r"(r2), "=r"(r3) : "r"(a));
}
__device__ __forceinline__ void mma_16816(float c[4],
                                          uint32_t a0, uint32_t a1, uint32_t a2, uint32_t a3,
                                          uint32_t b0, uint32_t b1) {
    asm volatile("mma.sync.aligned.m16n8k16.row.col.f32.f16.f16.f32 "
                 "{%0,%1,%2,%3}, {%4,%5,%6,%7}, {%8,%9}, {%0,%1,%2,%3};"
                 : "+f"(c[0]), "+f"(c[1]), "+f"(c[2]), "+f"(c[3])
                 : "r"(a0), "r"(a1), "r"(a2), "r"(a3), "r"(b0), "r"(b1));
}

__global__ void __launch_bounds__(NTHREADS, 1)
woq_fused_kernel(const float* __restrict__ x,
                 const int* __restrict__ qw,
                 const float* __restrict__ sz,
                 float* __restrict__ out)
{
    extern __shared__ char smem[];
    const uint32_t s_base = (uint32_t)__cvta_generic_to_shared(smem);
    const uint32_t raw_b  = s_base;                 // RING * WSTAGE
    const uint32_t as_b   = s_base + RING * WSTAGE; // RING * ASTAGE

    const int tid  = threadIdx.x;
    const int lane = tid & 31;
    const int warp = tid >> 5;
    const int wm   = warp & 3;
    const int wn   = warp >> 2;
    const int cta  = blockIdx.x;
    const int gtid = cta * NTHREADS + tid;
    const int GT   = NCTA * NTHREADS;   // 37888

    // ================= phase 0: prep (convert x, pack sz) =================
    for (int t = gtid; t < M_TOK * K_IN / 8; t += GT) {
        float4 v0 = *reinterpret_cast<const float4*>(x + (size_t)t * 8);
        float4 v1 = *reinterpret_cast<const float4*>(x + (size_t)t * 8 + 4);
        __half2 h0 = __floats2half2_rn(v0.x, v0.y);
        __half2 h1 = __floats2half2_rn(v0.z, v0.w);
        __half2 h2 = __floats2half2_rn(v1.x, v1.y);
        __half2 h3 = __floats2half2_rn(v1.z, v1.w);
        uint4 pk;
        pk.x = *reinterpret_cast<uint32_t*>(&h0);
        pk.y = *reinterpret_cast<uint32_t*>(&h1);
        pk.z = *reinterpret_cast<uint32_t*>(&h2);
        pk.w = *reinterpret_cast<uint32_t*>(&h3);
        *reinterpret_cast<uint4*>(g_xh + (size_t)t * 8) = pk;
    }
    for (int u = gtid; u < NG * N_OUT / 4; u += GT) {
        float4 v0 = *reinterpret_cast<const float4*>(sz + (size_t)u * 8);
        float4 v1 = *reinterpret_cast<const float4*>(sz + (size_t)u * 8 + 4);
        __half2 a = __floats2half2_rn(v0.x, v0.y);
        __half2 b = __floats2half2_rn(v0.z, v0.w);
        __half2 c2 = __floats2half2_rn(v1.x, v1.y);
        __half2 d = __floats2half2_rn(v1.z, v1.w);
        uint4 pk;
        pk.x = *reinterpret_cast<uint32_t*>(&a);
        pk.y = *reinterpret_cast<uint32_t*>(&b);
        pk.z = *reinterpret_cast<uint32_t*>(&c2);
        pk.w = *reinterpret_cast<uint32_t*>(&d);
        *reinterpret_cast<uint4*>(g_szp + (size_t)u * 4) = pk;
    }
    grid_sync(0);

    // ================= phase 1: stream-K GEMM =================
    const int w0 = gsplit(cta);
    const int w1 = gsplit(cta + 1);

    float acc[4][4];
    #pragma unroll
    for (int i = 0; i < 4; ++i)
        #pragma unroll
        for (int j = 0; j < 4; ++j) acc[i][j] = 0.f;

    // cp.async mappings
    const int wn_row = tid >> 2;             // 0..63 raw row
    const int wu0    = (tid & 3) * 8;        // first 16B unit in row
    const int xrow   = tid >> 4;             // 0..15
    const int xunit  = tid & 15;             // 16B unit

    // B fragment LDS base (per j add j*8*WROW), conflict-free via 528B row stagger
    const uint32_t b_lds = raw_b + (uint32_t)(wn * 32 + (lane >> 2)) * WROW + (lane & 3) * 8;
    // A ldmatrix offset within a stage
    const uint32_t a_rel = 2u * ((wm * 16 + (lane & 15)) * LDK + (lane >> 4) * 8);

    uint32_t szc[4], szn[4];
    const uint32_t* szpp = g_szp + wn * 32 + (lane >> 2);

    // stage loader: raw wq (8x16B) + x tile (4x16B) for work unit w into ring slot
    auto load_stage = [&](int w, int slot) {
        const int g  = w & (NG - 1);
        const int nb = (w >> 6) << 6;
        const int k0 = g * BK;
        const char* src = (const char*)(qw + (size_t)(nb + wn_row) * K_IN + k0) + wu0 * 16;
        uint32_t dst = raw_b + slot * WSTAGE + wn_row * WROW + wu0 * 16;
        #pragma unroll
        for (int u = 0; u < 8; ++u)
            cp16(dst + u * 16, src + u * 16);
        uint32_t ad = as_b + slot * ASTAGE + 2u * (xrow * LDK + xunit * 8);
        const __half* xs = g_xh + (size_t)xrow * K_IN + k0 + xunit * 8;
        #pragma unroll
        for (int j = 0; j < 4; ++j)
            cp16(ad + j * (16 * LDK * 2), xs + (size_t)j * 16 * K_IN);
    };

    // prologue: 3 stages + szp for chunk 0
    #pragma unroll
    for (int p = 0; p < 3; ++p) {
        if (w0 + p < w1) load_stage(w0 + p, p);
        asm volatile("cp.async.commit_group;");
    }
    {
        const int g = w0 & (NG - 1), nb = (w0 >> 6) << 6;
        #pragma unroll
        for (int j = 0; j < 4; ++j)
            szc[j] = __ldcg(szpp + (size_t)g * N_OUT + nb + j * 8);
    }

    const __half2 k1032 = __floats2half2_rn(1032.f, 1032.f);
    int seg = 0;

    for (int w = w0; w < w1; ++w) {
        const int i = w - w0;
        const int slot = i & (RING - 1);
        asm volatile("cp.async.wait_group 2;");
        __syncthreads();

        // issue stage i+3 (slot freed by last iter's barrier), always commit
        if (w + 3 < w1) load_stage(w + 3, (i + 3) & (RING - 1));
        asm volatile("cp.async.commit_group;");

        // prefetch szp for next chunk
        if (w + 1 < w1) {
            const int g = (w + 1) & (NG - 1), nb = ((w + 1) >> 6) << 6;
            #pragma unroll
            for (int j = 0; j < 4; ++j)
                szn[j] = __ldcg(szpp + (size_t)g * N_OUT + nb + j * 8);
        }

        // expand (s,z) for this chunk
        __half2 s2[4], z2[4];
        #pragma unroll
        for (int j = 0; j < 4; ++j) {
            const __half2 h = *reinterpret_cast<const __half2*>(&szc[j]);
            s2[j] = __half2half2(__low2half(h));
            z2[j] = __half2half2(__high2half(h));
        }

        const uint32_t rb = b_lds + slot * WSTAGE;
        const uint32_t ab = as_b + slot * ASTAGE + a_rel;

        #pragma unroll
        for (int kk = 0; kk < 8; ++kk) {
            uint32_t a0, a1, a2, a3;
            ldsm4(a0, a1, a2, a3, ab + kk * 32);
            #pragma unroll
            for (int j = 0; j < 4; ++j) {
                const uint32_t addr = rb + (uint32_t)j * (8 * WROW) + kk * 64;
                uint32_t q0, q1, q2, q3;
                lds2(q0, q1, addr);        // q[k], q[k+1]
                lds2(q2, q3, addr + 32);   // q[k+8], q[k+9]
                uint32_t p0 = 0x64006400u | q0 | (q1 << 16);
                uint32_t p1 = 0x64006400u | q2 | (q3 << 16);
                __half2 h0 = __hsub2(*reinterpret_cast<const __half2*>(&p0), k1032);
                __half2 h1 = __hsub2(*reinterpret_cast<const __half2*>(&p1), k1032);
                __half2 w0h = __hfma2(h0, s2[j], z2[j]);
                __half2 w1h = __hfma2(h1, s2[j], z2[j]);
                mma_16816(acc[j], a0, a1, a2, a3,
                          *reinterpret_cast<uint32_t*>(&w0h),
                          *reinterpret_cast<uint32_t*>(&w1h));
            }
        }

        #pragma unroll
        for (int j = 0; j < 4; ++j) szc[j] = szn[j];

        // segment boundary: write partial 64x64 block
        if (w + 1 == w1 || ((w + 1) >> 6) != (w >> 6)) {
            float* part = g_part + ((size_t)cta * 2 + seg) * 4096;
            const int row = wm * 16 + (lane >> 2);
            #pragma unroll
            for (int j = 0; j < 4; ++j) {
                const int col = wn * 32 + j * 8 + (lane & 3) * 2;
                *reinterpret_cast<float2*>(part + row * 64 + col) =
                    make_float2(acc[j][0], acc[j][1]);
                *reinterpret_cast<float2*>(part + (row + 8) * 64 + col) =
                    make_float2(acc[j][2], acc[j][3]);
                acc[j][0] = acc[j][1] = acc[j][2] = acc[j][3] = 0.f;
            }
            ++seg;
        }
    }

    grid_sync(1);

    // ================= phase 2: stream-K reduce =================
    for (int t = gtid; t < M_TOK * N_OUT / 2; t += GT) {
        const int i2 = t * 2;
        const int m  = i2 >> 13;
        const int n  = i2 & (N_OUT - 1);
        const int nt = n >> 6, nl = n & 63;
        const int X  = nt << 6;
        int c = (int)(((long long)X * NCTA) / WTOTAL);
        while (gsplit(c + 1) <= X) ++c;
        float sx = 0.f, sy = 0.f;
        while (c < NCTA && gsplit(c) < X + 64) {
            const int sg = ((gsplit(c) >> 6) == nt) ? 0 : 1;
            const float* p = g_part + ((size_t)c * 2 + sg) * 4096 + m * 64 + nl;
            sx += __ldcg(p);
            sy += __ldcg(p + 1);
            ++c;
        }
        *reinterpret_cast<float2*>(out + i2) = make_float2(sx, sy);
    }
}

extern "C" void kernel_launch(void* const* d_in, const int* in_sizes, int n_in,
                              void* d_out, int out_size) {
    const float* x  = (const float*)d_in[0];   // (64, 8192) fp32
    const int*   qw = (const int*)d_in[1];     // (8192, 8192) int32 in [0,15]
    const float* sz = (const float*)d_in[2];   // (64, 8192, 2) fp32
    float* out = (float*)d_out;                // (64, 8192) fp32

    cudaFuncSetAttribute(woq_fused_kernel,
                         cudaFuncAttributeMaxDynamicSharedMemorySize, SMEM_BYTES);
    woq_fused_kernel<<<NCTA, NTHREADS, SMEM_BYTES>>>(x, qw, sz, out);
}

// round 6
// speedup vs baseline: 2.2645x; 2.2645x over previous
#include <cuda_runtime.h>
#include <cuda_fp16.h>
#include <cstdint>

#define M_TOK 64
#define N_OUT 8192
#define K_IN  8192
#define NG    64            // K groups per row (8192/128)
#define NTILES (N_OUT / 64) // 128
#define WTOTAL (NTILES * NG)// 8192 work units
#define NCTA  296           // 2 per SM on 148 SMs, all resident (persistent)
#define BN    64
#define BK    128
#define LDK   136
#define NTHREADS 256
#define ABYTES (M_TOK * LDK * 2)
#define BBYTES (BN * LDK * 2)
#define SMEM_BYTES (2 * ABYTES + 2 * BBYTES)  // 69632 B -> 2 CTA/SM

__device__ __half   g_xh[M_TOK * K_IN];      // x in fp16 (1 MB)
__device__ uint32_t g_szp[NG * N_OUT];       // packed (s,z) half2 (2 MB)
__device__ float    g_part[NCTA * 2 * 4096]; // stream-K partials
__device__ unsigned g_syncctr[2];            // grid-sync tickets (monotonic across replays)

__device__ __forceinline__ int gsplit(int c) { return (int)(((long long)c * WTOTAL) / NCTA); }

__device__ __forceinline__ void grid_sync(int k) {
    __syncthreads();
    if (threadIdx.x == 0) {
        __threadfence();
        unsigned t = atomicAdd(&g_syncctr[k], 1u) + 1u;
        unsigned target = ((t + NCTA - 1u) / NCTA) * NCTA;
        while (atomicAdd(&g_syncctr[k], 0u) < target) __nanosleep(32);
        __threadfence();
    }
    __syncthreads();
}

__device__ __forceinline__ void cp16(uint32_t dst, const void* src) {
    asm volatile("cp.async.cg.shared.global [%0], [%1], 16;" :: "r"(dst), "l"(src));
}
__device__ __forceinline__ void ldsm4(uint32_t& r0, uint32_t& r1, uint32_t& r2, uint32_t& r3,
                                      uint32_t a) {
    asm volatile("ldmatrix.sync.aligned.m8n8.x4.shared.b16 {%0,%1,%2,%3}, [%4];"
                 : "=r"(r0), "=r"(r1), "=r"(r2), "=r"(r3) : "r"(a));
}
__device__ __forceinline__ void mma_16816(float c[4],
                                          uint32_t a0, uint32_t a1, uint32_t a2, uint32_t a3,
                                          uint32_t b0, uint32_t b1) {
    asm volatile("mma.sync.aligned.m16n8k16.row.col.f32.f16.f16.f32 "
                 "{%0,%1,%2,%3}, {%4,%5,%6,%7}, {%8,%9}, {%0,%1,%2,%3};"
                 : "+f"(c[0]), "+f"(c[1]), "+f"(c[2]), "+f"(c[3])
                 : "r"(a0), "r"(a1), "r"(a2), "r"(a3), "r"(b0), "r"(b1));
}

__global__ void __launch_bounds__(NTHREADS, 2)
woq_fused_kernel(const float* __restrict__ x,
                 const int* __restrict__ qw,
                 const float* __restrict__ sz,
                 float* __restrict__ out)
{
    extern __shared__ __half smem[];
    __half* Bs = smem + 2 * M_TOK * LDK;

    const int tid  = threadIdx.x;
    const int lane = tid & 31;
    const int warp = tid >> 5;
    const int wm   = warp & 3;
    const int wn   = warp >> 2;
    const int cta  = blockIdx.x;
    const int gtid = cta * NTHREADS + tid;
    const int GT   = NCTA * NTHREADS;  // 75776

    // ================= phase 0: prep (convert x, pack sz) =================
    for (int t = gtid; t < M_TOK * K_IN / 8; t += GT) {
        float4 v0 = *reinterpret_cast<const float4*>(x + (size_t)t * 8);
        float4 v1 = *reinterpret_cast<const float4*>(x + (size_t)t * 8 + 4);
        __half2 h0 = __floats2half2_rn(v0.x, v0.y);
        __half2 h1 = __floats2half2_rn(v0.z, v0.w);
        __half2 h2 = __floats2half2_rn(v1.x, v1.y);
        __half2 h3 = __floats2half2_rn(v1.z, v1.w);
        uint4 pk;
        pk.x = *reinterpret_cast<uint32_t*>(&h0);
        pk.y = *reinterpret_cast<uint32_t*>(&h1);
        pk.z = *reinterpret_cast<uint32_t*>(&h2);
        pk.w = *reinterpret_cast<uint32_t*>(&h3);
        *reinterpret_cast<uint4*>(g_xh + (size_t)t * 8) = pk;
    }
    for (int u = gtid; u < NG * N_OUT / 4; u += GT) {
        float4 v0 = *reinterpret_cast<const float4*>(sz + (size_t)u * 8);
        float4 v1 = *reinterpret_cast<const float4*>(sz + (size_t)u * 8 + 4);
        __half2 a = __floats2half2_rn(v0.x, v0.y);
        __half2 b = __floats2half2_rn(v0.z, v0.w);
        __half2 c2 = __floats2half2_rn(v1.x, v1.y);
        __half2 d = __floats2half2_rn(v1.z, v1.w);
        uint4 pk;
        pk.x = *reinterpret_cast<uint32_t*>(&a);
        pk.y = *reinterpret_cast<uint32_t*>(&b);
        pk.z = *reinterpret_cast<uint32_t*>(&c2);
        pk.w = *reinterpret_cast<uint32_t*>(&d);
        *reinterpret_cast<uint4*>(g_szp + (size_t)u * 4) = pk;
    }
    grid_sync(0);

    // ================= phase 1: stream-K GEMM (R4 structure) =================
    const int w0 = gsplit(cta);
    const int w1 = gsplit(cta + 1);

    float acc[4][4];
    #pragma unroll
    for (int i = 0; i < 4; ++i)
        #pragma unroll
        for (int j = 0; j < 4; ++j) acc[i][j] = 0.f;

    const uint32_t s_base = (uint32_t)__cvta_generic_to_shared(smem);
    const uint32_t as_b = s_base;
    const uint32_t bs_b = s_base + 2 * ABYTES;

    const uint32_t a_off  = as_b + 2u * ((wm * 16 + (lane & 15)) * LDK + (lane >> 4) * 8);
    const uint32_t b_off0 = bs_b + 2u * ((wn * 32 + (lane & 7) + ((lane >> 4) << 3)) * LDK
                                         + ((lane >> 3) & 1) * 8);
    const uint32_t b_off1 = b_off0 + 2u * 16 * LDK;

    const int xrow0 = tid >> 4;
    const int xcol  = tid & 15;
    const __half* xsrc = g_xh + (size_t)xrow0 * K_IN + xcol * 8;
    const uint32_t adst = as_b + 2u * (xrow0 * LDK + xcol * 8);

    int4     wq[8];
    uint32_t szr[8];

    // load chunk for work unit w into regs + As[pbuf]
    auto load_chunk = [&](int w, int pbuf) {
        const int g  = w & (NG - 1);
        const int nb = (w >> 6) << 6;
        const int k0 = g * BK;
        #pragma unroll
        for (int j = 0; j < 4; ++j)
            cp16(adst + pbuf * ABYTES + j * (16 * LDK * 2), xsrc + (size_t)j * 16 * K_IN + k0);
        asm volatile("cp.async.commit_group;");
        const int* qr = qw + (size_t)(nb + warp) * K_IN + k0 + lane * 4;
        #pragma unroll
        for (int it = 0; it < 8; ++it)
            wq[it] = *reinterpret_cast<const int4*>(qr + (size_t)(it * 8) * K_IN);
        const uint32_t* szp = g_szp + (size_t)g * N_OUT + nb + warp;
        #pragma unroll
        for (int it = 0; it < 8; ++it)
            szr[it] = __ldcg(szp + it * 8);
    };

    load_chunk(w0, 0);

    const __half2 k1032 = __floats2half2_rn(1032.f, 1032.f);
    int seg = 0;

    for (int w = w0; w < w1; ++w) {
        const int p = (w - w0) & 1;
        asm volatile("cp.async.wait_group 0;");

        // ---- dequant + stage w tile into Bs[p] ----
        __half* Bsb = Bs + p * (BN * LDK);
        #pragma unroll
        for (int it = 0; it < 8; ++it) {
            const int nloc = it * 8 + warp;
            const __half2 szh = *reinterpret_cast<const __half2*>(&szr[it]);
            const __half2 s2 = __half2half2(__low2half(szh));
            const __half2 z2 = __half2half2(__high2half(szh));
            const int4 q = wq[it];
            uint32_t p0 = 0x64006400u | (uint32_t)q.x | ((uint32_t)q.y << 16);
            uint32_t p1 = 0x64006400u | (uint32_t)q.z | ((uint32_t)q.w << 16);
            __half2 h0 = __hsub2(*reinterpret_cast<const __half2*>(&p0), k1032);
            __half2 h1 = __hsub2(*reinterpret_cast<const __half2*>(&p1), k1032);
            __half2 w0h = __hfma2(h0, s2, z2);
            __half2 w1h = __hfma2(h1, s2, z2);
            uint2 pk;
            pk.x = *reinterpret_cast<uint32_t*>(&w0h);
            pk.y = *reinterpret_cast<uint32_t*>(&w1h);
            *reinterpret_cast<uint2*>(&Bsb[nloc * LDK + lane * 4]) = pk;
        }
        __syncthreads();

        // ---- prefetch chunk w+1 (overlaps MMA) ----
        if (w + 1 < w1)
            load_chunk(w + 1, p ^ 1);

        // ---- MMA ----
        const uint32_t ab  = a_off  + p * ABYTES;
        const uint32_t bb0 = b_off0 + p * BBYTES;
        const uint32_t bb1 = b_off1 + p * BBYTES;
        #pragma unroll
        for (int kk = 0; kk < 8; ++kk) {
            uint32_t a0, a1, a2, a3;
            ldsm4(a0, a1, a2, a3, ab + kk * 32);
            uint32_t b0, b1, b2, b3, b4, b5, b6, b7;
            ldsm4(b0, b1, b2, b3, bb0 + kk * 32);
            ldsm4(b4, b5, b6, b7, bb1 + kk * 32);
            mma_16816(acc[0], a0, a1, a2, a3, b0, b1);
            mma_16816(acc[1], a0, a1, a2, a3, b2, b3);
            mma_16816(acc[2], a0, a1, a2, a3, b4, b5);
            mma_16816(acc[3], a0, a1, a2, a3, b6, b7);
        }

        // ---- segment boundary: write partial 64x64 block ----
        if (w + 1 == w1 || ((w + 1) >> 6) != (w >> 6)) {
            float* part = g_part + ((size_t)cta * 2 + seg) * 4096;
            const int row = wm * 16 + (lane >> 2);
            #pragma unroll
            for (int j = 0; j < 4; ++j) {
                const int col = wn * 32 + j * 8 + (lane & 3) * 2;
                *reinterpret_cast<float2*>(part + row * 64 + col) =
                    make_float2(acc[j][0], acc[j][1]);
                *reinterpret_cast<float2*>(part + (row + 8) * 64 + col) =
                    make_float2(acc[j][2], acc[j][3]);
                acc[j][0] = acc[j][1] = acc[j][2] = acc[j][3] = 0.f;
            }
            ++seg;
        }
    }

    grid_sync(1);

    // ================= phase 2: stream-K reduce =================
    for (int t = gtid; t < M_TOK * N_OUT / 2; t += GT) {
        const int i2 = t * 2;
        const int m  = i2 >> 13;
        const int n  = i2 & (N_OUT - 1);
        const int nt = n >> 6, nl = n & 63;
        const int X  = nt << 6;
        int c = (int)(((long long)X * NCTA) / WTOTAL);
        while (gsplit(c + 1) <= X) ++c;
        float sx = 0.f, sy = 0.f;
        while (c < NCTA && gsplit(c) < X + 64) {
            const int sg = ((gsplit(c) >> 6) == nt) ? 0 : 1;
            const float* pp = g_part + ((size_t)c * 2 + sg) * 4096 + m * 64 + nl;
            sx += __ldcg(pp);
            sy += __ldcg(pp + 1);
            ++c;
        }
        *reinterpret_cast<float2*>(out + i2) = make_float2(sx, sy);
    }
}

extern "C" void kernel_launch(void* const* d_in, const int* in_sizes, int n_in,
                              void* d_out, int out_size) {
    const float* x  = (const float*)d_in[0];   // (64, 8192) fp32
    const int*   qw = (const int*)d_in[1];     // (8192, 8192) int32 in [0,15]
    const float* sz = (const float*)d_in[2];   // (64, 8192, 2) fp32
    float* out = (float*)d_out;                // (64, 8192) fp32

    static bool attr_set = false;
    if (!attr_set) {
        cudaFuncSetAttribute(woq_fused_kernel,
                             cudaFuncAttributeMaxDynamicSharedMemorySize, SMEM_BYTES);
        attr_set = true;
    }
    woq_fused_kernel<<<NCTA, NTHREADS, SMEM_BYTES>>>(x, qw, sz, out);
}